// round 5
// baseline (speedup 1.0000x reference)
#include <cuda_runtime.h>
#include <cstdint>
#include <cstddef>

// Butterfly transform: B=8192 rows, N=4096, 12 stages, increasing stride.
// R5: occupancy attack. 6 rows/CTA (3 float2-packed pairs), 96KB smem,
// __launch_bounds__(512, 2) -> 2 CTAs/SM = 32 warps (was 16). One pair in
// flight at a time to fit the 64-reg budget; 48-reg twiddle cache per phase
// reused across the 3 pairs. Same 4 register-phases / 3 smem exchanges /
// conflict-free swizzle as the 86.5us R2 kernel.

namespace {
constexpr int kN       = 4096;
constexpr int kBatch   = 8192;
constexpr int kThreads = 512;
constexpr int kRows    = 6;
constexpr int kPairs   = kRows / 2;                         // 3
constexpr int kGrid    = 1366;                              // 1365 full + 1 tail(1 pair)
constexpr int kSmem    = kPairs * kN * (int)sizeof(float2); // 98304 B
}

// float2-granule swizzle; conflict-free for i = base + s*m, s in {1,8,64,512}.
__device__ __forceinline__ int swz(int i) {
    return (i & ~15) | ((i & 15) ^ ((i >> 4) & 7) ^ ((i >> 3) & 8));
}

// One 2x2 butterfly applied to two rows packed in float2 lanes.
__device__ __forceinline__ void bfly(float2& x0, float2& x1, const float4 tm) {
    float2 y0, y1;
    y0.x = __fmaf_rn(tm.y, x1.x, tm.x * x0.x);
    y0.y = __fmaf_rn(tm.y, x1.y, tm.x * x0.y);
    y1.x = __fmaf_rn(tm.w, x1.x, tm.z * x0.x);
    y1.y = __fmaf_rn(tm.w, x1.y, tm.z * x0.y);
    x0 = y0;
    x1 = y1;
}

// Three in-register substages over 8 owned elements (local strides 1,2,4).
__device__ __forceinline__ void substages(float2 v[8], const float4 twr[3][4]) {
    bfly(v[0], v[1], twr[0][0]); bfly(v[2], v[3], twr[0][1]);
    bfly(v[4], v[5], twr[0][2]); bfly(v[6], v[7], twr[0][3]);
    bfly(v[0], v[2], twr[1][0]); bfly(v[1], v[3], twr[1][1]);
    bfly(v[4], v[6], twr[1][2]); bfly(v[5], v[7], twr[1][3]);
    bfly(v[0], v[4], twr[2][0]); bfly(v[1], v[5], twr[2][1]);
    bfly(v[2], v[6], twr[2][2]); bfly(v[3], v[7], twr[2][3]);
}

template <int NPAIRS>
__device__ __forceinline__ void bf_body(const float* __restrict__ x,
                                        const float* __restrict__ tw,
                                        float* __restrict__ out,
                                        int row0, float2* buf) {
    const int t = threadIdx.x;
    const float4* tw4 = reinterpret_cast<const float4*>(tw);

    // ---------------- Phase 0: stages 0..2 (strides 1,2,4) ----------------
    {
        float4 twr[3][4];
        #pragma unroll
        for (int u = 0; u < 3; ++u)
            #pragma unroll
            for (int pm = 0; pm < 4; ++pm)
                twr[u][pm] = tw4[u * 2048 + 4 * t + pm];

        #pragma unroll
        for (int p = 0; p < NPAIRS; ++p) {
            const float4* xa =
                reinterpret_cast<const float4*>(x + (size_t)(row0 + 2 * p) * kN);
            const float4* xb =
                reinterpret_cast<const float4*>(x + (size_t)(row0 + 2 * p + 1) * kN);
            const float4 a0 = xa[2 * t], a1 = xa[2 * t + 1];
            const float4 b0 = xb[2 * t], b1 = xb[2 * t + 1];
            float2 v[8];
            v[0] = make_float2(a0.x, b0.x); v[1] = make_float2(a0.y, b0.y);
            v[2] = make_float2(a0.z, b0.z); v[3] = make_float2(a0.w, b0.w);
            v[4] = make_float2(a1.x, b1.x); v[5] = make_float2(a1.y, b1.y);
            v[6] = make_float2(a1.z, b1.z); v[7] = make_float2(a1.w, b1.w);

            substages(v, twr);

            float2* B = buf + p * kN;
            #pragma unroll
            for (int m = 0; m < 8; ++m) B[swz(8 * t + m)] = v[m];
        }
    }
    __syncthreads();

    // ------------- Phases 1,2: stages 3..8 (strides 8..256), smem ---------
    #pragma unroll
    for (int ph = 1; ph <= 2; ++ph) {
        const int ls = 3 * ph;          // 3 or 6
        const int s  = 1 << ls;         // 8 or 64
        const int b  = t >> ls;
        const int c  = t & (s - 1);
        const int base = b * 8 * s + c;

        float4 twr[3][4];
        #pragma unroll
        for (int u = 0; u < 3; ++u)
            #pragma unroll
            for (int pm = 0; pm < 4; ++pm)
                twr[u][pm] = tw4[(3 * ph + u) * 2048 + s * (4 * b + pm) + c];

        #pragma unroll
        for (int p = 0; p < NPAIRS; ++p) {
            float2* B = buf + p * kN;
            float2 v[8];
            #pragma unroll
            for (int m = 0; m < 8; ++m) v[m] = B[swz(base + s * m)];

            substages(v, twr);

            #pragma unroll
            for (int m = 0; m < 8; ++m) B[swz(base + s * m)] = v[m];
        }
        __syncthreads();
    }

    // ------------- Phase 3: stages 9..11 (strides 512..2048) -> out -------
    {
        const int s = 512;  // b = 0, c = t
        float4 twr[3][4];
        #pragma unroll
        for (int u = 0; u < 3; ++u)
            #pragma unroll
            for (int pm = 0; pm < 4; ++pm)
                twr[u][pm] = tw4[(9 + u) * 2048 + s * pm + t];

        #pragma unroll
        for (int p = 0; p < NPAIRS; ++p) {
            float2* B = buf + p * kN;
            float2 v[8];
            #pragma unroll
            for (int m = 0; m < 8; ++m) v[m] = B[swz(t + s * m)];

            substages(v, twr);

            float* oa = out + (size_t)(row0 + 2 * p) * kN;
            float* ob = oa + kN;
            #pragma unroll
            for (int m = 0; m < 8; ++m) {
                oa[t + s * m] = v[m].x;   // warp-contiguous 4B stores
                ob[t + s * m] = v[m].y;
            }
        }
    }
}

__global__ void __launch_bounds__(kThreads, 2)
butterfly_kernel(const float* __restrict__ x,
                 const float* __restrict__ tw,
                 float* __restrict__ out) {
    extern __shared__ float2 buf[];
    const int row0 = blockIdx.x * kRows;
    if (blockIdx.x < kGrid - 1) {
        bf_body<3>(x, tw, out, row0, buf);   // rows 0..8189
    } else {
        bf_body<1>(x, tw, out, row0, buf);   // rows 8190..8191
    }
}

extern "C" void kernel_launch(void* const* d_in, const int* in_sizes, int n_in,
                              void* d_out, int out_size) {
    const float* x  = (const float*)d_in[0];   // (8192, 4096) fp32
    const float* tw = (const float*)d_in[1];   // (1,1,12,2048,2,2) fp32
    float* out      = (float*)d_out;           // (8192, 4096) fp32

    cudaFuncSetAttribute(butterfly_kernel,
                         cudaFuncAttributeMaxDynamicSharedMemorySize, kSmem);
    butterfly_kernel<<<kGrid, kThreads, kSmem>>>(x, tw, out);
}

// round 6
// speedup vs baseline: 1.3429x; 1.3429x over previous
#include <cuda_runtime.h>
#include <cstdint>
#include <cstddef>

// Butterfly: B=8192 rows, N=4096, 12 stages, increasing stride.
// R6: warp-shuffle butterfly. i = hi*64+lo; stages 0-5 act on lo, 6-11 on hi.
// Each 64-point half is warp-internal: lane L holds slots (L, L+32); strides
// 1..16 via shfl_xor, stride 32 thread-local. One smem transpose exchange,
// 2 barriers/tile. 1024-thread CTA, 12 rows (6 float2 pairs, 192KB smem),
// ~60 regs -> 32 warps/SM. Twiddles pre-packed by a small kernel into a
// __device__ scratch: role-ordered (ta*mine + tb*partner) and lane-coalesced.

namespace {
constexpr int kN        = 4096;
constexpr int kBatch    = 8192;
constexpr int kThreads  = 1024;
constexpr int kTiles    = 683;               // 682 full (12 rows) + 1 tail (8 rows)
constexpr int kSmem     = 6 * kN * (int)sizeof(float2);  // 196608 B
constexpr int kTwPkN    = 2 * 64 * 6 * 32;   // float4 count = 24576 (393216 B)
}

// Packed twiddles: [phase(2)][group(64)][k(6)][lane(32)] float4
__device__ float4 g_twpk[kTwPkN];

// ---------------- Pre-pass: repack twiddles (runs per launch, ~3us) --------
__global__ void twpack_kernel(const float* __restrict__ tw) {
    const int idx = blockIdx.x * blockDim.x + threadIdx.x;
    if (idx >= kTwPkN) return;
    const int L   = idx & 31;
    int rest      = idx >> 5;
    const int k   = rest % 6;
    rest         /= 6;
    const int g   = rest & 63;   // phase A: hi group; phase B: lo value
    const int ph  = rest >> 6;

    float4 o;
    if (k == 5) {                // thread-local stage (stride 32 within half)
        const int u = ph ? 11 : 5;
        const int q = ph ? (L * 64 + g) : (g * 32 + L);
        const float* b = tw + (size_t)(u * 2048 + q) * 4;
        o = make_float4(b[0], b[1], b[2], b[3]);   // t00,t01,t10,t11
    } else {
        float2 e[2];
        #pragma unroll
        for (int h = 0; h < 2; ++h) {
            const int n   = 2 * k + h;   // 0..9
            const int sig = n / 5;       // slot
            const int u   = n % 5;       // substage (stride 2^u within half)
            const int pos = L + 32 * sig;
            const int s   = 1 << u;
            int q, su;
            if (ph == 0) {
                q  = g * 32 + (pos >> (u + 1)) * s + (pos & (s - 1));
                su = u;
            } else {
                q  = (pos >> (u + 1)) * (64 * s) + (pos & (s - 1)) * 64 + g;
                su = 6 + u;
            }
            const int bit = (pos >> u) & 1;
            const float* b = tw + (size_t)(su * 2048 + q) * 4;
            // role-ordered: out = ta*mine + tb*partner
            e[h] = bit ? make_float2(b[3], b[2]) : make_float2(b[0], b[1]);
        }
        o = make_float4(e[0].x, e[0].y, e[1].x, e[1].y);
    }
    g_twpk[idx] = o;
}

// ---------------- Main kernel ----------------------------------------------
// One shfl butterfly stage on a float2 (two rows share the twiddle).
__device__ __forceinline__ float2 bstage(float2 v, float ta, float tb, int s) {
    const float px = __shfl_xor_sync(0xffffffffu, v.x, s);
    const float py = __shfl_xor_sync(0xffffffffu, v.y, s);
    return make_float2(__fmaf_rn(tb, px, ta * v.x),
                       __fmaf_rn(tb, py, ta * v.y));
}

// 5 shfl substages + 1 local substage, per the packed twiddle layout.
__device__ __forceinline__ void half_butterfly(
    float2& v0, float2& v1,
    const float4 T0, const float4 T1, const float4 T2,
    const float4 T3, const float4 T4, const float4 T5) {
    v0 = bstage(v0, T0.x, T0.y, 1);  v1 = bstage(v1, T2.z, T2.w, 1);
    v0 = bstage(v0, T0.z, T0.w, 2);  v1 = bstage(v1, T3.x, T3.y, 2);
    v0 = bstage(v0, T1.x, T1.y, 4);  v1 = bstage(v1, T3.z, T3.w, 4);
    v0 = bstage(v0, T1.z, T1.w, 8);  v1 = bstage(v1, T4.x, T4.y, 8);
    v0 = bstage(v0, T2.x, T2.y, 16); v1 = bstage(v1, T4.z, T4.w, 16);
    // local stage (pair = the two slots)
    float2 n0, n1;
    n0.x = __fmaf_rn(T5.y, v1.x, T5.x * v0.x);
    n0.y = __fmaf_rn(T5.y, v1.y, T5.x * v0.y);
    n1.x = __fmaf_rn(T5.w, v1.x, T5.z * v0.x);
    n1.y = __fmaf_rn(T5.w, v1.y, T5.z * v0.y);
    v0 = n0; v1 = n1;
}

template <int NP>
__device__ __forceinline__ void tile_body(const float* __restrict__ x,
                                          float* __restrict__ out,
                                          int row0, float2* buf) {
    const int t    = threadIdx.x;
    const int warp = t >> 5;
    const int L    = t & 31;

    // ---------------- Phase A: stages 0..5 (within 64-el lo-blocks) --------
    #pragma unroll
    for (int gi = 0; gi < 2; ++gi) {
        const int g = warp + 32 * gi;                 // hi group
        const float4* tp = g_twpk + (size_t)g * 6 * 32 + L;
        const float4 T0 = tp[0],  T1 = tp[32],  T2 = tp[64];
        const float4 T3 = tp[96], T4 = tp[128], T5 = tp[160];
        const int a0 = g * 64 + (L ^ (g & 15));       // smem idx slot0

        #pragma unroll
        for (int p = 0; p < NP; ++p) {
            const float* rA = x + (size_t)(row0 + 2 * p) * kN + g * 64;
            const float* rB = rA + kN;
            float2 v0 = make_float2(rA[L],      rB[L]);
            float2 v1 = make_float2(rA[L + 32], rB[L + 32]);

            half_butterfly(v0, v1, T0, T1, T2, T3, T4, T5);

            buf[p * kN + a0]      = v0;
            buf[p * kN + a0 + 32] = v1;
        }
    }
    __syncthreads();

    // ---------------- Phase B: stages 6..11 (across hi, fixed lo) ----------
    #pragma unroll
    for (int gi = 0; gi < 2; ++gi) {
        const int lo0 = warp + 32 * gi;
        const float4* tp = g_twpk + (size_t)(64 + lo0) * 6 * 32 + L;
        const float4 T0 = tp[0],  T1 = tp[32],  T2 = tp[64];
        const float4 T3 = tp[96], T4 = tp[128], T5 = tp[160];
        const int c  = lo0 ^ (L & 15);                // (L+32)&15 == L&15
        const int b0 = L * 64 + c;                    // hi = L
        const int b1 = (L + 32) * 64 + c;             // hi = L+32

        #pragma unroll
        for (int p = 0; p < NP; ++p) {
            float2 v0 = buf[p * kN + b0];
            float2 v1 = buf[p * kN + b1];

            half_butterfly(v0, v1, T0, T1, T2, T3, T4, T5);

            buf[p * kN + b0] = v0;   // warp-exclusive elements: no barrier
            buf[p * kN + b1] = v1;
        }
    }
    __syncthreads();

    // ---------------- Final sweep: smem -> coalesced STG -------------------
    #pragma unroll
    for (int p = 0; p < NP; ++p) {
        float* oA = out + (size_t)(row0 + 2 * p) * kN;
        float* oB = oA + kN;
        #pragma unroll
        for (int m = 0; m < 4; ++m) {
            const int i = t + 1024 * m;
            const int a = (i & ~63) | ((i & 63) ^ ((i >> 6) & 15));
            const float2 v = buf[p * kN + a];
            oA[i] = v.x;
            oB[i] = v.y;
        }
    }
}

__global__ void __launch_bounds__(kThreads, 1)
butterfly_kernel(const float* __restrict__ x,
                 float* __restrict__ out) {
    extern __shared__ float2 buf[];
    const int row0 = blockIdx.x * 12;
    if (blockIdx.x < kTiles - 1) {
        tile_body<6>(x, out, row0, buf);   // rows 0..8183
    } else {
        tile_body<4>(x, out, row0, buf);   // rows 8184..8191
    }
}

extern "C" void kernel_launch(void* const* d_in, const int* in_sizes, int n_in,
                              void* d_out, int out_size) {
    const float* x  = (const float*)d_in[0];   // (8192, 4096) fp32
    const float* tw = (const float*)d_in[1];   // (1,1,12,2048,2,2) fp32
    float* out      = (float*)d_out;           // (8192, 4096) fp32

    twpack_kernel<<<(kTwPkN + 255) / 256, 256>>>(tw);

    cudaFuncSetAttribute(butterfly_kernel,
                         cudaFuncAttributeMaxDynamicSharedMemorySize, kSmem);
    butterfly_kernel<<<kTiles, kThreads, kSmem>>>(x, out);
}

// round 7
// speedup vs baseline: 1.3906x; 1.0355x over previous
#include <cuda_runtime.h>
#include <cstdint>
#include <cstddef>

// Butterfly: B=8192 rows, N=4096, 12 stages, increasing stride.
// R7: 1024-thread CTA (32 warps/SM), 12-row tile (6 float2 pairs, 192KB smem).
// Each thread owns 4 float2 per pair; each 3-stage phase = 2 register stages
// + 1 shfl_xor(1) stage (ownership chosen so the wide-stride partner is always
// thread t^1). Twiddle cache 24 regs, data 8 regs -> ~55 regs total, no spill.
// 3 smem exchanges, 3 barriers/tile, conflict-free XOR swizzle for all
// ownership patterns. FMA count identical to the 86.5us R2 kernel.

namespace {
constexpr int kN       = 4096;
constexpr int kThreads = 1024;
constexpr int kTiles   = 683;    // 682 full (12 rows) + 1 tail (8 rows)
constexpr int kSmem    = 6 * kN * (int)sizeof(float2);   // 196608 B
}

// Swizzle at float2 granularity. Bank-pair bits of sigma(i):
//   b0 = i0^i4, b1 = i1^i3, b2 = i2^i6^i9, b3 = i3^i5^i8^i11
// Verified conflict-free (16 distinct bank-pairs per half-warp) for the
// store/load patterns of all four phase ownerships. Bijective on [0,4096).
__device__ __forceinline__ int swz(int i) {
    const int f = ((i >> 4) & 1)
                | ((((i >> 3)) & 1) << 1)
                | ((((i >> 6) ^ (i >> 9)) & 1) << 2)
                | ((((i >> 5) ^ (i >> 8) ^ (i >> 11)) & 1) << 3);
    return i ^ f;
}

// twiddle row index for a butterfly at global stride 2^logS whose low element
// is lo:  q = (lo >> (logS+1)) << logS | (lo & (2^logS - 1))
__device__ __forceinline__ int twq(int lo, int logS) {
    return ((lo >> (logS + 1)) << logS) | (lo & ((1 << logS) - 1));
}

// One 2x2 butterfly on two rows packed in float2 lanes.
__device__ __forceinline__ void bfly(float2& x0, float2& x1, const float4 tm) {
    float2 y0, y1;
    y0.x = __fmaf_rn(tm.y, x1.x, tm.x * x0.x);
    y0.y = __fmaf_rn(tm.y, x1.y, tm.x * x0.y);
    y1.x = __fmaf_rn(tm.w, x1.x, tm.z * x0.x);
    y1.y = __fmaf_rn(tm.w, x1.y, tm.z * x0.y);
    x0 = y0;
    x1 = y1;
}

// Per-phase twiddle cache: 2 bflys at stride s, 2 at stride 2s, and 4
// role-selected (ta,tb) entries for the shfl stage at stride 4s.
struct PhaseTw {
    float4 tA0, tA1, tB0, tB1;
    float2 tC0, tC1, tC2, tC3;
};

template <int LOG_S>
__device__ __forceinline__ PhaseTw load_tw(const float4* __restrict__ tw4,
                                           int o, int z) {
    constexpr int s = 1 << LOG_S;
    PhaseTw T;
    T.tA0 = tw4[ LOG_S      * 2048 + twq(o,         LOG_S)];
    T.tA1 = tw4[ LOG_S      * 2048 + twq(o + 2 * s, LOG_S)];
    T.tB0 = tw4[(LOG_S + 1) * 2048 + twq(o,         LOG_S + 1)];
    T.tB1 = tw4[(LOG_S + 1) * 2048 + twq(o + s,     LOG_S + 1)];
    const int ob = o & ~(4 * s);          // clear the z bit -> low element
    float4 f;
    f = tw4[(LOG_S + 2) * 2048 + twq(ob,         LOG_S + 2)];
    T.tC0 = z ? make_float2(f.w, f.z) : make_float2(f.x, f.y);
    f = tw4[(LOG_S + 2) * 2048 + twq(ob + s,     LOG_S + 2)];
    T.tC1 = z ? make_float2(f.w, f.z) : make_float2(f.x, f.y);
    f = tw4[(LOG_S + 2) * 2048 + twq(ob + 2 * s, LOG_S + 2)];
    T.tC2 = z ? make_float2(f.w, f.z) : make_float2(f.x, f.y);
    f = tw4[(LOG_S + 2) * 2048 + twq(ob + 3 * s, LOG_S + 2)];
    T.tC3 = z ? make_float2(f.w, f.z) : make_float2(f.x, f.y);
    return T;
}

// shfl stage on one float2: out = ta*mine + tb*partner (role-ordered).
__device__ __forceinline__ void cstage(float2& v, const float2 tc) {
    const float px = __shfl_xor_sync(0xffffffffu, v.x, 1);
    const float py = __shfl_xor_sync(0xffffffffu, v.y, 1);
    v.x = __fmaf_rn(tc.y, px, tc.x * v.x);
    v.y = __fmaf_rn(tc.y, py, tc.x * v.y);
}

// 2 register stages + 1 shfl stage on the 4 owned float2 elements.
__device__ __forceinline__ void phase_math(float2 v[4], const PhaseTw& T) {
    bfly(v[0], v[1], T.tA0);  bfly(v[2], v[3], T.tA1);   // stride s
    bfly(v[0], v[2], T.tB0);  bfly(v[1], v[3], T.tB1);   // stride 2s
    cstage(v[0], T.tC0);  cstage(v[1], T.tC1);           // stride 4s (t^1)
    cstage(v[2], T.tC2);  cstage(v[3], T.tC3);
}

template <int NP>
__device__ __forceinline__ void tile_body(const float* __restrict__ x,
                                          float* __restrict__ out,
                                          const float4* __restrict__ tw4,
                                          float2* buf, int row0) {
    const int t = threadIdx.x;
    const int z = t & 1;

    // -------- Phase 0: stages 0..2 (strides 1,2,4). own i = 4t+m ----------
    {
        const PhaseTw T = load_tw<0>(tw4, 4 * t, z);
        int sw[4];
        #pragma unroll
        for (int m = 0; m < 4; ++m) sw[m] = swz(4 * t + m);

        #pragma unroll
        for (int p = 0; p < NP; ++p) {
            const float4 a = *reinterpret_cast<const float4*>(
                x + (size_t)(row0 + 2 * p) * kN + 4 * t);
            const float4 b = *reinterpret_cast<const float4*>(
                x + (size_t)(row0 + 2 * p + 1) * kN + 4 * t);
            float2 v[4] = { make_float2(a.x, b.x), make_float2(a.y, b.y),
                            make_float2(a.z, b.z), make_float2(a.w, b.w) };
            phase_math(v, T);
            float2* B = buf + p * kN;
            #pragma unroll
            for (int m = 0; m < 4; ++m) B[sw[m]] = v[m];
        }
    }
    __syncthreads();

    // -------- Phase 1: stages 3..5 (strides 8,16,32) -----------------------
    // own i = (t>>4)*64 + z*32 + ((t>>1)&7) + 8m ; stride-32 partner = t^1
    {
        const int o = ((t >> 4) << 6) + z * 32 + ((t >> 1) & 7);
        const PhaseTw T = load_tw<3>(tw4, o, z);
        int sw[4];
        #pragma unroll
        for (int m = 0; m < 4; ++m) sw[m] = swz(o + 8 * m);

        #pragma unroll
        for (int p = 0; p < NP; ++p) {
            float2* B = buf + p * kN;
            float2 v[4];
            #pragma unroll
            for (int m = 0; m < 4; ++m) v[m] = B[sw[m]];
            phase_math(v, T);
            #pragma unroll
            for (int m = 0; m < 4; ++m) B[sw[m]] = v[m];
        }
    }
    __syncthreads();

    // -------- Phase 2: stages 6..8 (strides 64,128,256) --------------------
    // own i = (t>>7)*512 + z*256 + ((t>>1)&63) + 64m ; partner = t^1
    {
        const int o = ((t >> 7) << 9) + z * 256 + ((t >> 1) & 63);
        const PhaseTw T = load_tw<6>(tw4, o, z);
        int sw[4];
        #pragma unroll
        for (int m = 0; m < 4; ++m) sw[m] = swz(o + 64 * m);

        #pragma unroll
        for (int p = 0; p < NP; ++p) {
            float2* B = buf + p * kN;
            float2 v[4];
            #pragma unroll
            for (int m = 0; m < 4; ++m) v[m] = B[sw[m]];
            phase_math(v, T);
            #pragma unroll
            for (int m = 0; m < 4; ++m) B[sw[m]] = v[m];
        }
    }
    __syncthreads();

    // -------- Phase 3: stages 9..11 (strides 512,1024,2048) -> gmem --------
    // own i = z*2048 + (t>>1) + 512m ; partner = t^1
    {
        const int o = z * 2048 + (t >> 1);
        const PhaseTw T = load_tw<9>(tw4, o, z);
        int sw[4];
        #pragma unroll
        for (int m = 0; m < 4; ++m) sw[m] = swz(o + 512 * m);

        #pragma unroll
        for (int p = 0; p < NP; ++p) {
            float2* B = buf + p * kN;
            float2 v[4];
            #pragma unroll
            for (int m = 0; m < 4; ++m) v[m] = B[sw[m]];
            phase_math(v, T);

            float* oa = out + (size_t)(row0 + 2 * p) * kN;
            float* ob = oa + kN;
            #pragma unroll
            for (int m = 0; m < 4; ++m) {
                oa[o + 512 * m] = v[m].x;
                ob[o + 512 * m] = v[m].y;
            }
        }
    }
}

__global__ void __launch_bounds__(kThreads, 1)
butterfly_kernel(const float* __restrict__ x,
                 const float* __restrict__ tw,
                 float* __restrict__ out) {
    extern __shared__ float2 buf[];
    const float4* tw4 = reinterpret_cast<const float4*>(tw);
    const int row0 = blockIdx.x * 12;
    if (blockIdx.x < kTiles - 1) {
        tile_body<6>(x, out, tw4, buf, row0);   // rows 0..8183
    } else {
        tile_body<4>(x, out, tw4, buf, row0);   // rows 8184..8191
    }
}

extern "C" void kernel_launch(void* const* d_in, const int* in_sizes, int n_in,
                              void* d_out, int out_size) {
    const float* x  = (const float*)d_in[0];   // (8192, 4096) fp32
    const float* tw = (const float*)d_in[1];   // (1,1,12,2048,2,2) fp32
    float* out      = (float*)d_out;           // (8192, 4096) fp32

    cudaFuncSetAttribute(butterfly_kernel,
                         cudaFuncAttributeMaxDynamicSharedMemorySize, kSmem);
    butterfly_kernel<<<kTiles, kThreads, kSmem>>>(x, tw, out);
}